// round 1
// baseline (speedup 1.0000x reference)
#include <cuda_runtime.h>
#include <math.h>

#define NN 50000
#define HH 128
#define TT 4
#define EE 150000
#define G3H 384

// ---------------- scratch (device globals: no allocation allowed) ----------
__device__ __align__(16) float g_h  [(size_t)NN * HH];        // current hidden state
__device__ __align__(16) float g_inc[(size_t)NN * HH];        // incoming messages
__device__ __align__(16) float g_S  [(size_t)TT * NN * HH];   // per-type raw-h scatter sums
__device__ __align__(16) float g_deg[(size_t)TT * NN];        // per-type in-degree (float)
__device__ __align__(16) float g_gx [(size_t)NN * G3H];
__device__ __align__(16) float g_gh [(size_t)NN * G3H];
__device__ __align__(16) float g_gxx[(size_t)NN * G3H];       // layer-1 constant x-part of gx

// ---------------- small utility kernels ------------------------------------
__global__ void zero4_kernel(float4* __restrict__ p, int n4) {
    int i = blockIdx.x * blockDim.x + threadIdx.x;
    if (i < n4) p[i] = make_float4(0.f, 0.f, 0.f, 0.f);
}

__global__ void copy4_kernel(float4* __restrict__ dst, const float4* __restrict__ src, int n4) {
    int i = blockIdx.x * blockDim.x + threadIdx.x;
    if (i < n4) dst[i] = src[i];
}

// ---------------- edge scatter: S_t[tgt] += h[src]; deg_t[tgt] += 1 --------
// one warp per edge; 32 lanes * float4 = 128 floats; vectorized red.global
__global__ void scatter_kernel(const int* __restrict__ edges,
                               const float* __restrict__ h,
                               float* __restrict__ S,
                               float* __restrict__ deg) {
    int e = blockIdx.x * 8 + (threadIdx.x >> 5);
    if (e >= TT * EE) return;
    int lane = threadIdx.x & 31;
    int t   = e / EE;
    int src = edges[2 * e];
    int tgt = edges[2 * e + 1];
    float4 v = *(const float4*)(h + (size_t)src * HH + lane * 4);
    float* dst = S + ((size_t)t * NN + (size_t)tgt) * HH + lane * 4;
    asm volatile("red.global.add.v4.f32 [%0], {%1, %2, %3, %4};"
                 :: "l"(dst), "f"(v.x), "f"(v.y), "f"(v.z), "f"(v.w)
                 : "memory");
    if (lane == 0) atomicAdd(deg + (size_t)t * NN + tgt, 1.0f);
}

// ---------------- inc[n][f] = sum_t deg[t][n] * b_l[t][f] ------------------
__global__ void inc_init_kernel(float* __restrict__ inc,
                                const float* __restrict__ deg,
                                const float* __restrict__ b) {
    int n = blockIdx.x;
    int f = threadIdx.x;
    float acc = 0.f;
#pragma unroll
    for (int t = 0; t < TT; t++)
        acc += deg[(size_t)t * NN + n] * b[t * HH + f];
    inc[(size_t)n * HH + f] = acc;
}

// ---------------- generic fp32 GEMM: C = (sum_tt A_tt @ B_tt^T) + Cin + bias
// A: M x K (row-major, stride lda), B: Ncols x K (row-major, stride ldb)
// blocktile 128x64, 256 threads, 8x4 microtile, K-tile 16
#define BM 128
#define BN 64
#define BK 16

__global__ __launch_bounds__(256)
void gemm_abt(const float* __restrict__ A, int lda, long strideAt,
              const float* __restrict__ B, int ldb, long strideBt, int TC,
              const float* __restrict__ Cin, float* __restrict__ C, int ldc,
              int M, int K, const float* __restrict__ bias) {
    __shared__ float As[BK][BM + 4];
    __shared__ float Bs[BK][BN + 4];

    int tid = threadIdx.x;
    int tx = tid & 15;   // column group (4 cols)
    int ty = tid >> 4;   // row group (8 rows)
    int row0 = blockIdx.y * BM;
    int col0 = blockIdx.x * BN;

    float acc[8][4];
#pragma unroll
    for (int i = 0; i < 8; i++)
#pragma unroll
        for (int j = 0; j < 4; j++) acc[i][j] = 0.f;

    int lr = tid >> 2;          // 0..63
    int lk = (tid & 3) << 2;    // 0,4,8,12

    for (int tt = 0; tt < TC; tt++) {
        const float* At = A + (long)tt * strideAt;
        const float* Bt = B + (long)tt * strideBt;
        for (int k0 = 0; k0 < K; k0 += BK) {
            // load A tile (128 x 16), two rows per thread
#pragma unroll
            for (int r = 0; r < 2; r++) {
                int ar = row0 + lr + r * 64;
                float4 v = make_float4(0.f, 0.f, 0.f, 0.f);
                if (ar < M) v = *(const float4*)(At + (long)ar * lda + k0 + lk);
                As[lk + 0][lr + r * 64] = v.x;
                As[lk + 1][lr + r * 64] = v.y;
                As[lk + 2][lr + r * 64] = v.z;
                As[lk + 3][lr + r * 64] = v.w;
            }
            // load B tile (64 x 16)
            {
                int br = col0 + lr;
                float4 v = *(const float4*)(Bt + (long)br * ldb + k0 + lk);
                Bs[lk + 0][lr] = v.x;
                Bs[lk + 1][lr] = v.y;
                Bs[lk + 2][lr] = v.z;
                Bs[lk + 3][lr] = v.w;
            }
            __syncthreads();
#pragma unroll
            for (int k = 0; k < BK; k++) {
                float4 a0 = *(const float4*)&As[k][ty * 8];
                float4 a1 = *(const float4*)&As[k][ty * 8 + 4];
                float4 b0 = *(const float4*)&Bs[k][tx * 4];
                float a[8] = {a0.x, a0.y, a0.z, a0.w, a1.x, a1.y, a1.z, a1.w};
                float b[4] = {b0.x, b0.y, b0.z, b0.w};
#pragma unroll
                for (int i = 0; i < 8; i++)
#pragma unroll
                    for (int j = 0; j < 4; j++)
                        acc[i][j] = fmaf(a[i], b[j], acc[i][j]);
            }
            __syncthreads();
        }
    }

#pragma unroll
    for (int i = 0; i < 8; i++) {
        int r = row0 + ty * 8 + i;
        if (r >= M) continue;
#pragma unroll
        for (int j = 0; j < 4; j++) {
            int c = col0 + tx * 4 + j;
            float v = acc[i][j];
            if (Cin)  v += Cin[(long)r * ldc + c];
            if (bias) v += bias[c];
            C[(long)r * ldc + c] = v;
        }
    }
}

// ---------------- GRU gate fusion (in-place h update) ----------------------
__global__ void gates_kernel(float* __restrict__ h,
                             const float* __restrict__ gx,
                             const float* __restrict__ gh) {
    int idx = blockIdx.x * blockDim.x + threadIdx.x;
    if (idx >= NN * HH) return;
    int n = idx >> 7;
    int f = idx & 127;
    long base = (long)n * G3H + f;
    float xr = gx[base], xz = gx[base + 128], xn = gx[base + 256];
    float hr = gh[base], hz = gh[base + 128], hn = gh[base + 256];
    float r = 1.f / (1.f + expf(-(xr + hr)));
    float z = 1.f / (1.f + expf(-(xz + hz)));
    float nn = tanhf(xn + r * hn);
    float hv = h[idx];
    h[idx] = (1.f - z) * nn + z * hv;
}

// ---------------- orchestration --------------------------------------------
extern "C" void kernel_launch(void* const* d_in, const int* in_sizes, int n_in,
                              void* d_out, int out_size) {
    const float* x      = (const float*)d_in[0];
    const int*   edges  = (const int*)  d_in[1];
    const float* msg_W  = (const float*)d_in[2];
    const float* msg_b  = (const float*)d_in[3];
    const float* g0Wih  = (const float*)d_in[4];
    const float* g0Whh  = (const float*)d_in[5];
    const float* g0bih  = (const float*)d_in[6];
    const float* g0bhh  = (const float*)d_in[7];
    const float* g1Wih  = (const float*)d_in[8];
    const float* g1Whh  = (const float*)d_in[9];
    const float* g1bih  = (const float*)d_in[10];
    const float* g1bhh  = (const float*)d_in[11];
    float* out = (float*)d_out;

    float *h, *inc, *S, *deg, *gx, *gh, *gxx;
    cudaGetSymbolAddress((void**)&h,   g_h);
    cudaGetSymbolAddress((void**)&inc, g_inc);
    cudaGetSymbolAddress((void**)&S,   g_S);
    cudaGetSymbolAddress((void**)&deg, g_deg);
    cudaGetSymbolAddress((void**)&gx,  g_gx);
    cudaGetSymbolAddress((void**)&gh,  g_gh);
    cudaGetSymbolAddress((void**)&gxx, g_gxx);

    const int nh4 = NN * HH / 4;                 // 1,600,000
    const int s4  = TT * NN * HH / 4;            // 25,600,000 / 4
    const int d4  = TT * NN / 4;                 // 50,000

    dim3 gridMsg(HH / BN,  (NN + BM - 1) / BM);  // (2, 391)
    dim3 gridG  (G3H / BN, (NN + BM - 1) / BM);  // (6, 391)

    // h = x
    copy4_kernel<<<(nh4 + 255) / 256, 256>>>((float4*)h, (const float4*)x, nh4);

    // layer-1 constant part: gxx = x @ Wih1[:, :128]^T + bih1
    gemm_abt<<<gridG, 256>>>(x, HH, 0, g1Wih, 2 * HH, 0, 1,
                             nullptr, gxx, G3H, NN, HH, g1bih);

    for (int l = 0; l < 2; l++) {
        for (int step = 0; step < 3; step++) {
            // zero scatter accumulators
            zero4_kernel<<<(s4 + 255) / 256, 256>>>((float4*)S, s4);
            zero4_kernel<<<(d4 + 255) / 256, 256>>>((float4*)deg, d4);

            // S_t[tgt] += h[src]; deg_t[tgt] += 1
            scatter_kernel<<<(TT * EE + 7) / 8, 256>>>(edges, h, S, deg);

            // inc = sum_t deg_t (x) b_t
            inc_init_kernel<<<NN, HH>>>(inc, deg, msg_b + (size_t)l * TT * HH);

            // inc += sum_t S_t @ W_{l,t}^T   (single launch, internal t-loop)
            gemm_abt<<<gridMsg, 256>>>(S, HH, (long)NN * HH,
                                       msg_W + (size_t)l * TT * HH * HH, HH, (long)HH * HH,
                                       TT, inc, inc, HH, NN, HH, nullptr);

            if (l == 0) {
                gemm_abt<<<gridG, 256>>>(inc, HH, 0, g0Wih, HH, 0, 1,
                                         nullptr, gx, G3H, NN, HH, g0bih);
                gemm_abt<<<gridG, 256>>>(h, HH, 0, g0Whh, HH, 0, 1,
                                         nullptr, gh, G3H, NN, HH, g0bhh);
            } else {
                // gx = gxx + inc @ Wih1[:, 128:]^T
                gemm_abt<<<gridG, 256>>>(inc, HH, 0, g1Wih + HH, 2 * HH, 0, 1,
                                         gxx, gx, G3H, NN, HH, nullptr);
                gemm_abt<<<gridG, 256>>>(h, HH, 0, g1Whh, HH, 0, 1,
                                         nullptr, gh, G3H, NN, HH, g1bhh);
            }

            // GRU gates, h updated in place
            gates_kernel<<<(NN * HH + 255) / 256, 256>>>(h, gx, gh);
        }
    }

    // out = h
    copy4_kernel<<<(nh4 + 255) / 256, 256>>>((float4*)out, (const float4*)h, nh4);
}

// round 7
// speedup vs baseline: 2.0794x; 2.0794x over previous
#include <cuda_runtime.h>
#include <cstdint>
#include <math.h>

#define NN 50000
#define HH 128
#define TT 4
#define EE 150000
#define G3H 384

// ---------------- scratch ---------------------------------------------------
__device__ __align__(16) float g_h  [(size_t)NN * HH];
__device__ __align__(16) float g_inc[(size_t)NN * HH];
__device__ __align__(16) float g_m  [(size_t)TT * NN * HH];
__device__ __align__(16) float g_gx [(size_t)NN * G3H];
__device__ __align__(16) float g_gh [(size_t)NN * G3H];
__device__ __align__(16) float g_gxx[(size_t)NN * G3H];

// ---------------- utility kernels ------------------------------------------
__global__ void zero4_kernel(float4* __restrict__ p, int n4) {
    int i = blockIdx.x * blockDim.x + threadIdx.x;
    if (i < n4) p[i] = make_float4(0.f, 0.f, 0.f, 0.f);
}
__global__ void copy4_kernel(float4* __restrict__ dst, const float4* __restrict__ src, int n4) {
    int i = blockIdx.x * blockDim.x + threadIdx.x;
    if (i < n4) dst[i] = src[i];
}

// ---------------- scatter: inc[tgt] += m[t][src] ---------------------------
__global__ void scatter_kernel(const int* __restrict__ edges,
                               const float* __restrict__ m,
                               float* __restrict__ inc) {
    int e = blockIdx.x * 8 + (threadIdx.x >> 5);
    if (e >= TT * EE) return;
    int lane = threadIdx.x & 31;
    int t   = e / EE;
    int src = edges[2 * e];
    int tgt = edges[2 * e + 1];
    float4 v = *(const float4*)(m + ((size_t)t * NN + (size_t)src) * HH + lane * 4);
    float* dst = inc + (size_t)tgt * HH + lane * 4;
    asm volatile("red.global.add.v4.f32 [%0], {%1, %2, %3, %4};"
                 :: "l"(dst), "f"(v.x), "f"(v.y), "f"(v.z), "f"(v.w)
                 : "memory");
}

// ---------------- tf32 mma.sync GEMM: C = A @ B^T (+bias +Cin) -------------
// A: [M,128] row-major (lda = 128). B: [Ncols,K] rows with stride ldb.
// One CTA per 128x128 output tile; 256 threads; warp = 64x32 microtile.
// K = 128 processed as 2 chunks of 64 through smem.

#define KCH 64
#define SPITCH 68                      // floats; (68*r + c) % 32 == (4r+c)%32
#define ATILE (128 * SPITCH)           // uint32 elems
#define GEMM_SMEM (2 * ATILE * 4)      // 69632 bytes

extern __shared__ uint32_t gsm[];

__device__ __forceinline__ void mma8(float* d, const uint32_t* a, const uint32_t* b) {
    asm volatile(
        "mma.sync.aligned.m16n8k8.row.col.f32.tf32.tf32.f32 "
        "{%0,%1,%2,%3}, {%4,%5,%6,%7}, {%8,%9}, {%0,%1,%2,%3};"
        : "+f"(d[0]), "+f"(d[1]), "+f"(d[2]), "+f"(d[3])
        : "r"(a[0]), "r"(a[1]), "r"(a[2]), "r"(a[3]), "r"(b[0]), "r"(b[1]));
}

__global__ __launch_bounds__(256, 2)
void gemm_tc(const float* __restrict__ A,
             const float* __restrict__ B, int ldb, long sBz,
             const float* __restrict__ Cin,
             float* __restrict__ C, int ldc, long sCz,
             const float* __restrict__ bias, int sBiasZ,
             int M) {
    uint32_t* As = gsm;
    uint32_t* Bs = gsm + ATILE;

    int tid  = threadIdx.x;
    int wid  = tid >> 5;
    int lane = tid & 31;
    int wm   = wid & 1;        // 0..1 : 64-row group
    int wn   = wid >> 1;       // 0..3 : 32-col group
    int g    = lane >> 2;      // 0..7
    int tg   = lane & 3;       // 0..3

    int z    = blockIdx.z;
    int row0 = blockIdx.y * 128;
    int col0 = blockIdx.x * 128;
    const float* Bz = B + (long)z * sBz;
    float* Cz = C + (long)z * sCz;

    float acc[4][4][4];
#pragma unroll
    for (int i = 0; i < 4; i++)
#pragma unroll
        for (int j = 0; j < 4; j++)
#pragma unroll
            for (int k = 0; k < 4; k++) acc[i][j][k] = 0.f;

    for (int kc = 0; kc < 128; kc += KCH) {
        // ---- load chunk: A[128][64], B[128][64] -> smem (tf32, RNA) ----
#pragma unroll
        for (int i = 0; i < 8; i++) {
            int id = tid + 256 * i;
            int r  = id >> 4;
            int c4 = (id & 15) << 2;
            float4 va = make_float4(0.f, 0.f, 0.f, 0.f);
            if (row0 + r < M) va = *(const float4*)(A + (long)(row0 + r) * HH + kc + c4);
            uint4 ua;
            asm("cvt.rna.tf32.f32 %0, %1;" : "=r"(ua.x) : "f"(va.x));
            asm("cvt.rna.tf32.f32 %0, %1;" : "=r"(ua.y) : "f"(va.y));
            asm("cvt.rna.tf32.f32 %0, %1;" : "=r"(ua.z) : "f"(va.z));
            asm("cvt.rna.tf32.f32 %0, %1;" : "=r"(ua.w) : "f"(va.w));
            *(uint4*)(As + r * SPITCH + c4) = ua;

            float4 vb = *(const float4*)(Bz + (long)(col0 + r) * ldb + kc + c4);
            uint4 ub;
            asm("cvt.rna.tf32.f32 %0, %1;" : "=r"(ub.x) : "f"(vb.x));
            asm("cvt.rna.tf32.f32 %0, %1;" : "=r"(ub.y) : "f"(vb.y));
            asm("cvt.rna.tf32.f32 %0, %1;" : "=r"(ub.z) : "f"(vb.z));
            asm("cvt.rna.tf32.f32 %0, %1;" : "=r"(ub.w) : "f"(vb.w));
            *(uint4*)(Bs + r * SPITCH + c4) = ub;
        }
        __syncthreads();

        // ---- 8 k-steps of 8 over this chunk ----
#pragma unroll
        for (int ks = 0; ks < 8; ks++) {
            int k0 = ks * 8;
            uint32_t af[4][4], bf[4][2];
#pragma unroll
            for (int mt = 0; mt < 4; mt++) {
                int r = wm * 64 + mt * 16 + g;
                af[mt][0] = As[(r    ) * SPITCH + k0 + tg];
                af[mt][1] = As[(r + 8) * SPITCH + k0 + tg];
                af[mt][2] = As[(r    ) * SPITCH + k0 + tg + 4];
                af[mt][3] = As[(r + 8) * SPITCH + k0 + tg + 4];
            }
#pragma unroll
            for (int nt = 0; nt < 4; nt++) {
                int c = wn * 32 + nt * 8 + g;
                bf[nt][0] = Bs[c * SPITCH + k0 + tg];
                bf[nt][1] = Bs[c * SPITCH + k0 + tg + 4];
            }
#pragma unroll
            for (int mt = 0; mt < 4; mt++)
#pragma unroll
                for (int nt = 0; nt < 4; nt++)
                    mma8(acc[mt][nt], af[mt], bf[nt]);
        }
        __syncthreads();
    }

    // ---- epilogue: direct stores with bias / Cin fusion ----
#pragma unroll
    for (int mt = 0; mt < 4; mt++) {
        int r = row0 + wm * 64 + mt * 16 + g;
#pragma unroll
        for (int nt = 0; nt < 4; nt++) {
            int c = col0 + wn * 32 + nt * 8 + 2 * tg;
            float b0 = 0.f, b1 = 0.f;
            if (bias) {
                const float* bz = bias + (long)z * sBiasZ + c;
                b0 = bz[0]; b1 = bz[1];
            }
            if (r < M) {
                float v0 = acc[mt][nt][0] + b0;
                float v1 = acc[mt][nt][1] + b1;
                if (Cin) {
                    float2 ci = *(const float2*)(Cin + (long)r * ldc + c);
                    v0 += ci.x; v1 += ci.y;
                }
                *(float2*)(Cz + (long)r * ldc + c) = make_float2(v0, v1);
            }
            if (r + 8 < M) {
                float v2 = acc[mt][nt][2] + b0;
                float v3 = acc[mt][nt][3] + b1;
                if (Cin) {
                    float2 ci = *(const float2*)(Cin + (long)(r + 8) * ldc + c);
                    v2 += ci.x; v3 += ci.y;
                }
                *(float2*)(Cz + (long)(r + 8) * ldc + c) = make_float2(v2, v3);
            }
        }
    }
}

// ---------------- GRU gate fusion ------------------------------------------
__global__ void gates_kernel(float* __restrict__ h,
                             const float* __restrict__ gx,
                             const float* __restrict__ gh) {
    int idx = blockIdx.x * blockDim.x + threadIdx.x;
    if (idx >= NN * HH) return;
    int n = idx >> 7;
    int f = idx & 127;
    long base = (long)n * G3H + f;
    float xr = gx[base], xz = gx[base + 128], xn = gx[base + 256];
    float hr = gh[base], hz = gh[base + 128], hn = gh[base + 256];
    float r = 1.f / (1.f + expf(-(xr + hr)));
    float z = 1.f / (1.f + expf(-(xz + hz)));
    float nn = tanhf(xn + r * hn);
    float hv = h[idx];
    h[idx] = (1.f - z) * nn + z * hv;
}

// ---------------- orchestration --------------------------------------------
extern "C" void kernel_launch(void* const* d_in, const int* in_sizes, int n_in,
                              void* d_out, int out_size) {
    const float* x      = (const float*)d_in[0];
    const int*   edges  = (const int*)  d_in[1];
    const float* msg_W  = (const float*)d_in[2];
    const float* msg_b  = (const float*)d_in[3];
    const float* g0Wih  = (const float*)d_in[4];
    const float* g0Whh  = (const float*)d_in[5];
    const float* g0bih  = (const float*)d_in[6];
    const float* g0bhh  = (const float*)d_in[7];
    const float* g1Wih  = (const float*)d_in[8];
    const float* g1Whh  = (const float*)d_in[9];
    const float* g1bih  = (const float*)d_in[10];
    const float* g1bhh  = (const float*)d_in[11];
    float* out = (float*)d_out;

    float *h, *inc, *m, *gx, *gh, *gxx;
    cudaGetSymbolAddress((void**)&h,   g_h);
    cudaGetSymbolAddress((void**)&inc, g_inc);
    cudaGetSymbolAddress((void**)&m,   g_m);
    cudaGetSymbolAddress((void**)&gx,  g_gx);
    cudaGetSymbolAddress((void**)&gh,  g_gh);
    cudaGetSymbolAddress((void**)&gxx, g_gxx);

    static int smem_set = 0;
    if (!smem_set) {
        cudaFuncSetAttribute(gemm_tc, cudaFuncAttributeMaxDynamicSharedMemorySize, GEMM_SMEM);
        smem_set = 1;
    }

    const int nh4 = NN * HH / 4;

    dim3 gridMsg(1, 391, TT);   // m_t = h @ W_t^T + b_t
    dim3 gridG  (3, 391, 1);    // 384-wide outputs

    // h = x
    copy4_kernel<<<(nh4 + 255) / 256, 256>>>((float4*)h, (const float4*)x, nh4);

    // gxx = x @ Wih1[:, :128]^T + bih1
    gemm_tc<<<gridG, 256, GEMM_SMEM>>>(x, g1Wih, 2 * HH, 0, nullptr,
                                       gxx, G3H, 0, g1bih, 0, NN);

    for (int l = 0; l < 2; l++) {
        for (int step = 0; step < 3; step++) {
            // m_t = h @ W_{l,t}^T + b_{l,t}
            gemm_tc<<<gridMsg, 256, GEMM_SMEM>>>(h,
                                                 msg_W + (size_t)l * TT * HH * HH, HH, (long)HH * HH,
                                                 nullptr,
                                                 m, HH, (long)NN * HH,
                                                 msg_b + (size_t)l * TT * HH, HH, NN);

            // inc = 0; inc[tgt] += m_t[src]
            zero4_kernel<<<(nh4 + 255) / 256, 256>>>((float4*)inc, nh4);
            scatter_kernel<<<(TT * EE + 7) / 8, 256>>>(edges, m, inc);

            if (l == 0) {
                gemm_tc<<<gridG, 256, GEMM_SMEM>>>(inc, g0Wih, HH, 0, nullptr,
                                                   gx, G3H, 0, g0bih, 0, NN);
                gemm_tc<<<gridG, 256, GEMM_SMEM>>>(h, g0Whh, HH, 0, nullptr,
                                                   gh, G3H, 0, g0bhh, 0, NN);
            } else {
                gemm_tc<<<gridG, 256, GEMM_SMEM>>>(inc, g1Wih + HH, 2 * HH, 0, gxx,
                                                   gx, G3H, 0, nullptr, 0, NN);
                gemm_tc<<<gridG, 256, GEMM_SMEM>>>(h, g1Whh, HH, 0, nullptr,
                                                   gh, G3H, 0, g1bhh, 0, NN);
            }

            gates_kernel<<<(NN * HH + 255) / 256, 256>>>(h, gx, gh);
        }
    }

    copy4_kernel<<<(nh4 + 255) / 256, 256>>>((float4*)out, (const float4*)h, nh4);
}